// round 15
// baseline (speedup 1.0000x reference)
#include <cuda_runtime.h>
#include <cstdint>

// SpecEMA single-pass decoupled-lookback scan. R13 base (LCH=40, 6 blocks/SM,
// TMA tiles, warp-parallel windowed lookback, agg fallback) with ONE change:
// the lookback is hoisted BEFORE the TMA-data wait so the two latencies overlap.
#define BB 64
#define CC 2
#define TT 4000
#define FF 96
#define NF4 24
#define NSUB 8
#define LS 5
#define LCH (NSUB * LS)      // 40
#define NCH (TT / LCH)       // 100
#define NTHR (NSUB * NF4)    // 192
#define GRID (BB * NCH)      // 6400
#define TILE_C_BYTES (LCH * FF * 4)   // 15360 per channel (contiguous)

#define ALPHA_F 0.99f
#define OMA_F ((float)(1.0 - 0.99))   // float32(1 - 0.99), matches jax

__host__ __device__ constexpr float fpow(float a, int n) {
    float r = 1.0f;
    for (int i = 0; i < n; i++) r *= a;
    return r;
}

// ---- scratch (__device__ globals; allocation-free; zero-initialized) ----
__device__ float4 g_agg[GRID * NF4];
__device__ float4 g_inc[GRID * NF4];
__device__ unsigned g_flag[GRID];    // gen-coded: 2*gen+1 = agg, 2*gen+2 = inc
__device__ unsigned g_ctr;           // monotone across graph replays

__device__ __forceinline__ unsigned ld_acquire(const unsigned* p) {
    unsigned v;
    asm volatile("ld.global.acquire.gpu.b32 %0, [%1];" : "=r"(v) : "l"(p));
    return v;
}
__device__ __forceinline__ void st_release(unsigned* p, unsigned v) {
    asm volatile("st.global.release.gpu.b32 [%0], %1;" :: "l"(p), "r"(v));
}
__device__ __forceinline__ uint32_t smem_u32(const void* p) {
    return (uint32_t)__cvta_generic_to_shared(p);
}
__device__ __forceinline__ void mbar_init(uint32_t mbar, uint32_t cnt) {
    asm volatile("mbarrier.init.shared.b64 [%0], %1;" :: "r"(mbar), "r"(cnt) : "memory");
}
__device__ __forceinline__ void mbar_expect_tx(uint32_t mbar, uint32_t bytes) {
    asm volatile("mbarrier.arrive.expect_tx.shared.b64 _, [%0], %1;"
                 :: "r"(mbar), "r"(bytes) : "memory");
}
__device__ __forceinline__ void mbar_wait_parity0(uint32_t mbar) {
    asm volatile(
        "{\n\t.reg .pred P1;\n\t"
        "WAIT_LOOP_%=:\n\t"
        "mbarrier.try_wait.parity.acquire.cta.shared::cta.b64 P1, [%0], 0, 0x989680;\n\t"
        "@P1 bra.uni WAIT_DONE_%=;\n\t"
        "bra.uni WAIT_LOOP_%=;\n\t"
        "WAIT_DONE_%=:\n\t}"
        :: "r"(mbar) : "memory");
}
__device__ __forceinline__ void bulk_ld(uint32_t smem_dst, const void* gsrc,
                                        uint32_t bytes, uint32_t mbar) {
    asm volatile("cp.async.bulk.shared::cta.global.mbarrier::complete_tx::bytes "
                 "[%0], [%1], %2, [%3];"
                 :: "r"(smem_dst), "l"(gsrc), "r"(bytes), "r"(mbar) : "memory");
}
__device__ __forceinline__ void bulk_st(void* gdst, uint32_t smem_src, uint32_t bytes) {
    asm volatile("cp.async.bulk.global.shared::cta.bulk_group [%0], [%1], %2;"
                 :: "l"(gdst), "r"(smem_src), "r"(bytes) : "memory");
}

#define EMA4(s, a, c)                                                        \
    (s).x = fmaf(fmaf((a).x, (a).x, (c).x * (c).x), OMA_F, (s).x * ALPHA_F); \
    (s).y = fmaf(fmaf((a).y, (a).y, (c).y * (c).y), OMA_F, (s).y * ALPHA_F); \
    (s).z = fmaf(fmaf((a).z, (a).z, (c).z * (c).z), OMA_F, (s).z * ALPHA_F); \
    (s).w = fmaf(fmaf((a).w, (a).w, (c).w * (c).w), OMA_F, (s).w * ALPHA_F)

// parameter tokens chosen to never collide with float4 members (R9 lesson)
#define FMA4(acc, W_, V_)                      \
    (acc).x = fmaf((W_), (V_).x, (acc).x);     \
    (acc).y = fmaf((W_), (V_).y, (acc).y);     \
    (acc).z = fmaf((W_), (V_).z, (acc).z);     \
    (acc).w = fmaf((W_), (V_).w, (acc).w)

#define FOLD4(S_, A_, P_)                      \
    (S_).x = fmaf((A_), (S_).x, (P_).x);       \
    (S_).y = fmaf((A_), (S_).y, (P_).y);       \
    (S_).z = fmaf((A_), (S_).z, (P_).z);       \
    (S_).w = fmaf((A_), (S_).w, (P_).w)

__global__ void __launch_bounds__(NTHR, 6)
k_scan(const float* __restrict__ x,
       const float* __restrict__ state,
       float* __restrict__ out,
       float* __restrict__ fstate,
       int write_state) {
    __shared__ alignas(128) float4 xs[CC][LCH][NF4];  // 30720 B
    __shared__ float4 sX[NSUB][NF4];   // lookback window, then partials (reused)
    __shared__ unsigned sSt[NSUB];
    __shared__ uint64_t mbar;
    __shared__ unsigned s_vbid;

    const int tid = threadIdx.x;
    const uint32_t mb = smem_u32(&mbar);
    if (tid == 0) {
        s_vbid = atomicAdd(&g_ctr, 1u);
        mbar_init(mb, 1);
    }
    __syncthreads();
    const unsigned raw = s_vbid;
    const unsigned gen = raw / (unsigned)GRID;
    const int vbid = (int)(raw % (unsigned)GRID);
    const unsigned V_AGG = 2u * gen + 1u;
    const unsigned V_INC = 2u * gen + 2u;

    const int b   = vbid % BB;        // b fastest: predecessors scheduled first
    const int j   = vbid / BB;
    const int f4  = tid % NF4;
    const int sub = tid / NF4;

    const int g0 = ((b * CC + 0) * TT + j * LCH) * FF;
    const int g1 = ((b * CC + 1) * TT + j * LCH) * FF;

    // ---- issue TMA loads immediately ----
    if (tid == 0) {
        mbar_expect_tx(mb, 2 * TILE_C_BYTES);
        bulk_ld(smem_u32(&xs[0][0][0]), x + g0, TILE_C_BYTES, mb);
        bulk_ld(smem_u32(&xs[1][0][0]), x + g1, TILE_C_BYTES, mb);
    }

    const float aLS = fpow(ALPHA_F, LS);    // alpha^5
    const float aB  = fpow(ALPHA_F, LCH);   // alpha^40
    const int ch = b * NCH + j;
    const float4 state4 = *(const float4*)(state + f4 * 4);

    // ==== windowed lookback, OVERLAPPED with the in-flight TMA load ====
    // (needs only predecessor flags/values; agg fallback keeps it non-serial)
    float4 S;
    if (j == 0) {
        S = state4;
    } else {
        float4 acc = make_float4(0.f, 0.f, 0.f, 0.f);
        float w = 1.0f;                // aB^(depth of window base)
        int base = j - 1;
        for (;;) {
            const int k = base - sub;
            // step 1: ONE leader per sub observes the flag (single truth point)
            if (f4 == 0 && k >= 0) {
                const unsigned* fl = &g_flag[b * NCH + k];
                unsigned st = ld_acquire(fl);
                int spins = 0;
                while (st < V_AGG) {
                    if (++spins > 32) { __nanosleep(64); spins = 0; }
                    st = ld_acquire(fl);
                }
                sSt[sub] = (st == V_INC) ? 2u : 1u;
            }
            __syncthreads();   // relay leader's acquire to the whole block

            // step 2: all threads load the value per the SHARED status
            // (g_agg is never overwritten; AGG status stays valid even if the
            //  flag advanced to INC after the leader's read)
            if (k >= 0) {
                float4 v = (sSt[sub] == 2u) ? g_inc[(b * NCH + k) * NF4 + f4]
                                            : g_agg[(b * NCH + k) * NF4 + f4];
                sX[sub][f4] = v;
            }
            __syncthreads();

            // step 3: uniform combine over the window
            const int lim = (base < NSUB - 1) ? base : (NSUB - 1);
            float wcur = w;
            bool done = false;
            for (int s = 0; s <= lim; s++) {
                float4 v = sX[s][f4];
                unsigned stv = sSt[s];
                FMA4(acc, wcur, v);
                if (stv == 2u) { done = true; break; }       // inclusive found
                if (base - s == 0) {                          // consumed chunk-0 agg
                    float ws = wcur * aB;
                    FMA4(acc, ws, state4);
                    done = true; break;
                }
                wcur *= aB;
            }
            __syncthreads();           // window consumed before next rewrite
            if (done) break;
            base -= NSUB;              // guaranteed >= 0 here
            w = wcur;                  // = previous w * aB^NSUB
        }
        S = acc;
    }

    // ---- wait for tile data (mostly already arrived during lookback) ----
    mbar_wait_parity0(mb);

    // ---- phase 1: per-sub partial EMA from s=0 ----
    float4 P = make_float4(0.f, 0.f, 0.f, 0.f);
#pragma unroll
    for (int t = 0; t < LS; t++) {
        float4 a = xs[0][sub * LS + t][f4];
        float4 c = xs[1][sub * LS + t][f4];
        EMA4(P, a, c);
    }
    sX[sub][f4] = P;       // window fully consumed (barrier after combine)
    __syncthreads();

    // A = full fold; Q = prefix fold up to own sub (start = aLS^sub * S + Q)
    float4 A = make_float4(0.f, 0.f, 0.f, 0.f);
    float4 Q = make_float4(0.f, 0.f, 0.f, 0.f);
    float aPow = 1.0f;                 // aLS^sub
#pragma unroll
    for (int k = 0; k < NSUB; k++) {
        float4 Pk = sX[k][f4];
        FOLD4(A, aLS, Pk);
        if (k < sub) { FOLD4(Q, aLS, Pk); aPow *= aLS; }
    }

    // ---- publish agg, then inclusive immediately (S already resolved) ----
    if (sub == 0) {                    // tids 0..23, warp 0
        g_agg[ch * NF4 + f4] = A;
        __syncwarp(0x00FFFFFFu);
        if (tid == 0) { __threadfence(); st_release(&g_flag[ch], V_AGG); }
        float4 inc;
        inc.x = fmaf(aB, S.x, A.x);
        inc.y = fmaf(aB, S.y, A.y);
        inc.z = fmaf(aB, S.z, A.z);
        inc.w = fmaf(aB, S.w, A.w);
        g_inc[ch * NF4 + f4] = inc;
        __syncwarp(0x00FFFFFFu);
        if (tid == 0) { __threadfence(); st_release(&g_flag[ch], V_INC); }
    }

    // ---- start state: s4 = aLS^sub * S + Q ----
    float4 s4;
    s4.x = fmaf(aPow, S.x, Q.x);
    s4.y = fmaf(aPow, S.y, Q.y);
    s4.z = fmaf(aPow, S.z, Q.z);
    s4.w = fmaf(aPow, S.w, Q.w);

    // ---- phase 3: replay, compute y in place in smem ----
#pragma unroll
    for (int t = 0; t < LS; t++) {
        float4 a = xs[0][sub * LS + t][f4];
        float4 c = xs[1][sub * LS + t][f4];
        EMA4(s4, a, c);
        float4 r;
        r.x = rsqrtf(s4.x); r.y = rsqrtf(s4.y);
        r.z = rsqrtf(s4.z); r.w = rsqrtf(s4.w);
        float4 y0, y1;
        y0.x = a.x * r.x; y0.y = a.y * r.y; y0.z = a.z * r.z; y0.w = a.w * r.w;
        y1.x = c.x * r.x; y1.y = c.y * r.y; y1.z = c.z * r.z; y1.w = c.w * r.w;
        xs[0][sub * LS + t][f4] = y0;
        xs[1][sub * LS + t][f4] = y1;
    }

    if (write_state && j == NCH - 1 && sub == NSUB - 1) {
        *(float4*)(fstate + b * FF + f4 * 4) = s4;
    }

    __syncthreads();
    asm volatile("fence.proxy.async.shared::cta;" ::: "memory");
    if (tid == 0) {
        bulk_st(out + g0, smem_u32(&xs[0][0][0]), TILE_C_BYTES);
        bulk_st(out + g1, smem_u32(&xs[1][0][0]), TILE_C_BYTES);
        asm volatile("cp.async.bulk.commit_group;" ::: "memory");
        asm volatile("cp.async.bulk.wait_group 0;" ::: "memory");
    }
}

extern "C" void kernel_launch(void* const* d_in, const int* in_sizes, int n_in,
                              void* d_out, int out_size) {
    const float* feat  = (const float*)d_in[0];   // [B,C,T,F] f32
    const float* state = (const float*)d_in[1];   // [1,1,F]   f32
    float* out = (float*)d_out;

    const int n_out_main = BB * CC * TT * FF;     // 49,152,000
    int write_state = (out_size >= n_out_main + BB * FF) ? 1 : 0;
    float* fstate = out + n_out_main;

    k_scan<<<GRID, NTHR>>>(feat, state, out, fstate, write_state);
}

// round 16
// speedup vs baseline: 3.5570x; 3.5570x over previous
#include <cuda_runtime.h>
#include <cstdint>

// SpecEMA decoupled-lookback scan. R13 compute path unchanged; a dedicated
// 7th warp runs the windowed lookback concurrently with the TMA flight and
// phase1. Invariant kept: agg publish never waits on any lookback.
#define BB 64
#define CC 2
#define TT 4000
#define FF 96
#define NF4 24
#define NSUB 8
#define LS 5
#define LCH (NSUB * LS)      // 40
#define NCH (TT / LCH)       // 100
#define NTHR_C 192           // compute threads (warps 0-5)
#define NTHR_TOT 224         // + lookback warp (warp 6)
#define GRID (BB * NCH)      // 6400
#define TILE_C_BYTES (LCH * FF * 4)   // 15360 per channel (contiguous)

#define ALPHA_F 0.99f
#define OMA_F ((float)(1.0 - 0.99))   // float32(1 - 0.99), matches jax

__host__ __device__ constexpr float fpow(float a, int n) {
    float r = 1.0f;
    for (int i = 0; i < n; i++) r *= a;
    return r;
}

// ---- scratch (__device__ globals; allocation-free; zero-initialized) ----
__device__ float4 g_agg[GRID * NF4];
__device__ float4 g_inc[GRID * NF4];
__device__ unsigned g_flag[GRID];    // gen-coded: 2*gen+1 = agg, 2*gen+2 = inc
__device__ unsigned g_ctr;           // monotone across graph replays

__device__ __forceinline__ unsigned ld_acquire(const unsigned* p) {
    unsigned v;
    asm volatile("ld.global.acquire.gpu.b32 %0, [%1];" : "=r"(v) : "l"(p));
    return v;
}
__device__ __forceinline__ void st_release(unsigned* p, unsigned v) {
    asm volatile("st.global.release.gpu.b32 [%0], %1;" :: "l"(p), "r"(v));
}
__device__ __forceinline__ uint32_t smem_u32(const void* p) {
    return (uint32_t)__cvta_generic_to_shared(p);
}
__device__ __forceinline__ void mbar_init(uint32_t mbar, uint32_t cnt) {
    asm volatile("mbarrier.init.shared.b64 [%0], %1;" :: "r"(mbar), "r"(cnt) : "memory");
}
__device__ __forceinline__ void mbar_expect_tx(uint32_t mbar, uint32_t bytes) {
    asm volatile("mbarrier.arrive.expect_tx.shared.b64 _, [%0], %1;"
                 :: "r"(mbar), "r"(bytes) : "memory");
}
__device__ __forceinline__ void mbar_wait_parity0(uint32_t mbar) {
    asm volatile(
        "{\n\t.reg .pred P1;\n\t"
        "WAIT_LOOP_%=:\n\t"
        "mbarrier.try_wait.parity.acquire.cta.shared::cta.b64 P1, [%0], 0, 0x989680;\n\t"
        "@P1 bra.uni WAIT_DONE_%=;\n\t"
        "bra.uni WAIT_LOOP_%=;\n\t"
        "WAIT_DONE_%=:\n\t}"
        :: "r"(mbar) : "memory");
}
__device__ __forceinline__ void bulk_ld(uint32_t smem_dst, const void* gsrc,
                                        uint32_t bytes, uint32_t mbar) {
    asm volatile("cp.async.bulk.shared::cta.global.mbarrier::complete_tx::bytes "
                 "[%0], [%1], %2, [%3];"
                 :: "r"(smem_dst), "l"(gsrc), "r"(bytes), "r"(mbar) : "memory");
}
__device__ __forceinline__ void bulk_st(void* gdst, uint32_t smem_src, uint32_t bytes) {
    asm volatile("cp.async.bulk.global.shared::cta.bulk_group [%0], [%1], %2;"
                 :: "l"(gdst), "r"(smem_src), "r"(bytes) : "memory");
}

// named barriers: 1 = compute warps only (192), 2 = all warps (224)
#define BAR_COMPUTE() asm volatile("bar.sync 1, 192;" ::: "memory")
#define BAR_ALL()     asm volatile("bar.sync 2, 224;" ::: "memory")

#define EMA4(s, a, c)                                                        \
    (s).x = fmaf(fmaf((a).x, (a).x, (c).x * (c).x), OMA_F, (s).x * ALPHA_F); \
    (s).y = fmaf(fmaf((a).y, (a).y, (c).y * (c).y), OMA_F, (s).y * ALPHA_F); \
    (s).z = fmaf(fmaf((a).z, (a).z, (c).z * (c).z), OMA_F, (s).z * ALPHA_F); \
    (s).w = fmaf(fmaf((a).w, (a).w, (c).w * (c).w), OMA_F, (s).w * ALPHA_F)

// parameter tokens never collide with float4 members (R9 lesson)
#define FMA4(acc, W_, V_)                      \
    (acc).x = fmaf((W_), (V_).x, (acc).x);     \
    (acc).y = fmaf((W_), (V_).y, (acc).y);     \
    (acc).z = fmaf((W_), (V_).z, (acc).z);     \
    (acc).w = fmaf((W_), (V_).w, (acc).w)

#define FOLD4(S_, A_, P_)                      \
    (S_).x = fmaf((A_), (S_).x, (P_).x);       \
    (S_).y = fmaf((A_), (S_).y, (P_).y);       \
    (S_).z = fmaf((A_), (S_).z, (P_).z);       \
    (S_).w = fmaf((A_), (S_).w, (P_).w)

__global__ void __launch_bounds__(NTHR_TOT, 6)
k_scan(const float* __restrict__ x,
       const float* __restrict__ state,
       float* __restrict__ out,
       float* __restrict__ fstate,
       int write_state) {
    __shared__ alignas(128) float4 xs[CC][LCH][NF4];  // 30720 B
    __shared__ float4 sP[NSUB][NF4];   // phase-1 partials
    __shared__ float4 sA[NF4];         // block aggregate (for lookback warp)
    __shared__ float4 sS[NF4];         // resolved prefix state (from lookback warp)
    __shared__ uint64_t mbar;
    __shared__ unsigned s_vbid;

    const int tid = threadIdx.x;
    const uint32_t mb = smem_u32(&mbar);
    if (tid == 0) {
        s_vbid = atomicAdd(&g_ctr, 1u);
        mbar_init(mb, 1);
    }
    __syncthreads();                  // all 224 threads (pre-divergence)
    const unsigned raw = s_vbid;
    const unsigned gen = raw / (unsigned)GRID;
    const int vbid = (int)(raw % (unsigned)GRID);
    const unsigned V_AGG = 2u * gen + 1u;
    const unsigned V_INC = 2u * gen + 2u;

    const int b = vbid % BB;          // b fastest: predecessors scheduled first
    const int j = vbid / BB;
    const int ch = b * NCH + j;

    const int g0 = ((b * CC + 0) * TT + j * LCH) * FF;
    const int g1 = ((b * CC + 1) * TT + j * LCH) * FF;

    if (tid == 0) {
        mbar_expect_tx(mb, 2 * TILE_C_BYTES);
        bulk_ld(smem_u32(&xs[0][0][0]), x + g0, TILE_C_BYTES, mb);
        bulk_ld(smem_u32(&xs[1][0][0]), x + g1, TILE_C_BYTES, mb);
    }

    const float aLS = fpow(ALPHA_F, LS);    // alpha^5
    const float aB  = fpow(ALPHA_F, LCH);   // alpha^40

    if (tid >= NTHR_C) {
        // ================= LOOKBACK WARP (warp 6) =================
        const int lane = tid - NTHR_C;       // 0..31
        const bool vlane = lane < NF4;       // 24 value lanes (lane == f4)
        float4 state4 = make_float4(0.f, 0.f, 0.f, 0.f);
        if (vlane) state4 = *(const float4*)(state + lane * 4);

        float4 S = state4;
        if (j > 0) {
            float4 acc = make_float4(0.f, 0.f, 0.f, 0.f);
            float w = 1.0f;
            int base = j - 1;
            for (;;) {
                const int lim = (base < NSUB - 1) ? base : (NSUB - 1);
                // lanes 0..7: observe predecessor flags (single truth point)
                unsigned myst = 0u;
                {
                    const int k = base - lane;
                    if (lane < NSUB && k >= 0) {
                        const unsigned* fl = &g_flag[b * NCH + k];
                        unsigned st = ld_acquire(fl);
                        int spins = 0;
                        while (st < V_AGG) {
                            if (++spins > 32) { __nanosleep(64); spins = 0; }
                            st = ld_acquire(fl);
                        }
                        myst = (st == V_INC) ? 2u : 1u;
                    }
                }
                __syncwarp();
                unsigned stv[NSUB];
#pragma unroll
                for (int s = 0; s < NSUB; s++)
                    stv[s] = __shfl_sync(0xffffffffu, myst, s);

                // prefetch all slot values (batched -> 1 L2 RTT, not 8)
                float4 vv[NSUB];
#pragma unroll
                for (int s = 0; s < NSUB; s++) {
                    if (vlane && s <= lim) {
                        const int kk = base - s;
                        vv[s] = (stv[s] == 2u) ? g_inc[(b * NCH + kk) * NF4 + lane]
                                               : g_agg[(b * NCH + kk) * NF4 + lane];
                    }
                }
                // combine (status pattern identical across lanes)
                float wcur = w;
                bool done = false;
                for (int s = 0; s <= lim; s++) {
                    if (vlane) FMA4(acc, wcur, vv[s]);
                    if (stv[s] == 2u) { done = true; break; }
                    if (base - s == 0) {
                        if (vlane) { float ws = wcur * aB; FMA4(acc, ws, state4); }
                        done = true; break;
                    }
                    wcur *= aB;
                }
                if (done) break;
                base -= NSUB;
                w = wcur;
            }
            S = acc;
        }
        if (vlane) sS[lane] = S;

        BAR_ALL();                            // join compute warps (A in sA)

        // publish inclusive (agg already out; inc unblocks successors fully)
        if (vlane) {
            float4 A = sA[lane];
            float4 inc;
            inc.x = fmaf(aB, S.x, A.x);
            inc.y = fmaf(aB, S.y, A.y);
            inc.z = fmaf(aB, S.z, A.z);
            inc.w = fmaf(aB, S.w, A.w);
            g_inc[ch * NF4 + lane] = inc;
        }
        __syncwarp();
        if (lane == 0) { __threadfence(); st_release(&g_flag[ch], V_INC); }
        // warp 6 done (does not participate in store barriers)
    } else {
        // ================= COMPUTE WARPS (0-5): R13 path =================
        const int f4  = tid % NF4;
        const int sub = tid / NF4;

        mbar_wait_parity0(mb);

        // phase 1: per-sub partial EMA from s=0
        float4 P = make_float4(0.f, 0.f, 0.f, 0.f);
#pragma unroll
        for (int t = 0; t < LS; t++) {
            float4 a = xs[0][sub * LS + t][f4];
            float4 c = xs[1][sub * LS + t][f4];
            EMA4(P, a, c);
        }
        sP[sub][f4] = P;
        BAR_COMPUTE();

        // A = full fold; Q = prefix fold up to own sub
        float4 A = make_float4(0.f, 0.f, 0.f, 0.f);
        float4 Q = make_float4(0.f, 0.f, 0.f, 0.f);
        float aPow = 1.0f;                 // aLS^sub
#pragma unroll
        for (int k = 0; k < NSUB; k++) {
            float4 Pk = sP[k][f4];
            FOLD4(A, aLS, Pk);
            if (k < sub) { FOLD4(Q, aLS, Pk); aPow *= aLS; }
        }

        // publish aggregate immediately — independent of any lookback
        if (sub == 0) {                    // tids 0..23, warp 0
            g_agg[ch * NF4 + f4] = A;
            __syncwarp(0x00FFFFFFu);
            if (tid == 0) { __threadfence(); st_release(&g_flag[ch], V_AGG); }
            sA[f4] = A;                    // hand A to the lookback warp
        }

        BAR_ALL();                         // sS now holds the prefix state S

        float4 S = sS[f4];
        float4 s4;
        s4.x = fmaf(aPow, S.x, Q.x);
        s4.y = fmaf(aPow, S.y, Q.y);
        s4.z = fmaf(aPow, S.z, Q.z);
        s4.w = fmaf(aPow, S.w, Q.w);

        // phase 3: replay, compute y in place in smem
#pragma unroll
        for (int t = 0; t < LS; t++) {
            float4 a = xs[0][sub * LS + t][f4];
            float4 c = xs[1][sub * LS + t][f4];
            EMA4(s4, a, c);
            float4 r;
            r.x = rsqrtf(s4.x); r.y = rsqrtf(s4.y);
            r.z = rsqrtf(s4.z); r.w = rsqrtf(s4.w);
            float4 y0, y1;
            y0.x = a.x * r.x; y0.y = a.y * r.y; y0.z = a.z * r.z; y0.w = a.w * r.w;
            y1.x = c.x * r.x; y1.y = c.y * r.y; y1.z = c.z * r.z; y1.w = c.w * r.w;
            xs[0][sub * LS + t][f4] = y0;
            xs[1][sub * LS + t][f4] = y1;
        }

        if (write_state && j == NCH - 1 && sub == NSUB - 1) {
            *(float4*)(fstate + b * FF + f4 * 4) = s4;
        }

        BAR_COMPUTE();                     // all compute writes to xs done
        asm volatile("fence.proxy.async.shared::cta;" ::: "memory");
        if (tid == 0) {
            bulk_st(out + g0, smem_u32(&xs[0][0][0]), TILE_C_BYTES);
            bulk_st(out + g1, smem_u32(&xs[1][0][0]), TILE_C_BYTES);
            asm volatile("cp.async.bulk.commit_group;" ::: "memory");
            asm volatile("cp.async.bulk.wait_group 0;" ::: "memory");
        }
    }
}

extern "C" void kernel_launch(void* const* d_in, const int* in_sizes, int n_in,
                              void* d_out, int out_size) {
    const float* feat  = (const float*)d_in[0];   // [B,C,T,F] f32
    const float* state = (const float*)d_in[1];   // [1,1,F]   f32
    float* out = (float*)d_out;

    const int n_out_main = BB * CC * TT * FF;     // 49,152,000
    int write_state = (out_size >= n_out_main + BB * FF) ? 1 : 0;
    float* fstate = out + n_out_main;

    k_scan<<<GRID, NTHR_TOT>>>(feat, state, out, fstate, write_state);
}

// round 17
// speedup vs baseline: 4.3498x; 1.2229x over previous
#include <cuda_runtime.h>
#include <cstdint>

// SpecEMA single-pass decoupled-lookback scan. R13 structure exactly, with
// LCH 40->80 (double-size items): half the per-byte fixed costs, same
// 36 warps/SM (3 blocks x 384 thr). Tile in dynamic smem (68KB > 48KB static).
#define BB 64
#define CC 2
#define TT 4000
#define FF 96
#define NF4 24
#define NSUB 16
#define LS 5
#define LCH (NSUB * LS)      // 80
#define NCH (TT / LCH)       // 50
#define NTHR (NSUB * NF4)    // 384
#define GRID (BB * NCH)      // 3200
#define TILE_C_BYTES (LCH * FF * 4)            // 30720 per channel
#define XS_F4 (CC * LCH * NF4)                 // tile float4 count
#define DSMEM (XS_F4 * 16 + NSUB * NF4 * 16)   // 61440 + 6144 = 67584

#define ALPHA_F 0.99f
#define OMA_F ((float)(1.0 - 0.99))   // float32(1 - 0.99), matches jax

__host__ __device__ constexpr float fpow(float a, int n) {
    float r = 1.0f;
    for (int i = 0; i < n; i++) r *= a;
    return r;
}

// ---- scratch (__device__ globals; allocation-free; zero-initialized) ----
__device__ float4 g_agg[GRID * NF4];
__device__ float4 g_inc[GRID * NF4];
__device__ unsigned g_flag[GRID];    // gen-coded: 2*gen+1 = agg, 2*gen+2 = inc
__device__ unsigned g_ctr;           // monotone across graph replays

__device__ __forceinline__ unsigned ld_acquire(const unsigned* p) {
    unsigned v;
    asm volatile("ld.global.acquire.gpu.b32 %0, [%1];" : "=r"(v) : "l"(p));
    return v;
}
__device__ __forceinline__ void st_release(unsigned* p, unsigned v) {
    asm volatile("st.global.release.gpu.b32 [%0], %1;" :: "l"(p), "r"(v));
}
__device__ __forceinline__ uint32_t smem_u32(const void* p) {
    return (uint32_t)__cvta_generic_to_shared(p);
}
__device__ __forceinline__ void mbar_init(uint32_t mbar, uint32_t cnt) {
    asm volatile("mbarrier.init.shared.b64 [%0], %1;" :: "r"(mbar), "r"(cnt) : "memory");
}
__device__ __forceinline__ void mbar_expect_tx(uint32_t mbar, uint32_t bytes) {
    asm volatile("mbarrier.arrive.expect_tx.shared.b64 _, [%0], %1;"
                 :: "r"(mbar), "r"(bytes) : "memory");
}
__device__ __forceinline__ void mbar_wait_parity0(uint32_t mbar) {
    asm volatile(
        "{\n\t.reg .pred P1;\n\t"
        "WAIT_LOOP_%=:\n\t"
        "mbarrier.try_wait.parity.acquire.cta.shared::cta.b64 P1, [%0], 0, 0x989680;\n\t"
        "@P1 bra.uni WAIT_DONE_%=;\n\t"
        "bra.uni WAIT_LOOP_%=;\n\t"
        "WAIT_DONE_%=:\n\t}"
        :: "r"(mbar) : "memory");
}
__device__ __forceinline__ void bulk_ld(uint32_t smem_dst, const void* gsrc,
                                        uint32_t bytes, uint32_t mbar) {
    asm volatile("cp.async.bulk.shared::cta.global.mbarrier::complete_tx::bytes "
                 "[%0], [%1], %2, [%3];"
                 :: "r"(smem_dst), "l"(gsrc), "r"(bytes), "r"(mbar) : "memory");
}
__device__ __forceinline__ void bulk_st(void* gdst, uint32_t smem_src, uint32_t bytes) {
    asm volatile("cp.async.bulk.global.shared::cta.bulk_group [%0], [%1], %2;"
                 :: "l"(gdst), "r"(smem_src), "r"(bytes) : "memory");
}

#define EMA4(s, a, c)                                                        \
    (s).x = fmaf(fmaf((a).x, (a).x, (c).x * (c).x), OMA_F, (s).x * ALPHA_F); \
    (s).y = fmaf(fmaf((a).y, (a).y, (c).y * (c).y), OMA_F, (s).y * ALPHA_F); \
    (s).z = fmaf(fmaf((a).z, (a).z, (c).z * (c).z), OMA_F, (s).z * ALPHA_F); \
    (s).w = fmaf(fmaf((a).w, (a).w, (c).w * (c).w), OMA_F, (s).w * ALPHA_F)

// parameter tokens never collide with float4 members (R9 lesson)
#define FMA4(acc, W_, V_)                      \
    (acc).x = fmaf((W_), (V_).x, (acc).x);     \
    (acc).y = fmaf((W_), (V_).y, (acc).y);     \
    (acc).z = fmaf((W_), (V_).z, (acc).z);     \
    (acc).w = fmaf((W_), (V_).w, (acc).w)

#define FOLD4(S_, A_, P_)                      \
    (S_).x = fmaf((A_), (S_).x, (P_).x);       \
    (S_).y = fmaf((A_), (S_).y, (P_).y);       \
    (S_).z = fmaf((A_), (S_).z, (P_).z);       \
    (S_).w = fmaf((A_), (S_).w, (P_).w)

__global__ void __launch_bounds__(NTHR, 3)
k_scan(const float* __restrict__ x,
       const float* __restrict__ state,
       float* __restrict__ out,
       float* __restrict__ fstate,
       int write_state) {
    extern __shared__ float4 dyn[];    // [XS_F4] tile | [NSUB*NF4] window
    float4* xs = dyn;                  // xs[c][t][f4] = dyn[(c*LCH+t)*NF4+f4]
    float4* sX = dyn + XS_F4;          // partials / lookback window
    __shared__ unsigned sSt[NSUB];
    __shared__ uint64_t mbar;
    __shared__ unsigned s_vbid;

    const int tid = threadIdx.x;
    const uint32_t mb = smem_u32(&mbar);
    if (tid == 0) {
        s_vbid = atomicAdd(&g_ctr, 1u);
        mbar_init(mb, 1);
    }
    __syncthreads();
    const unsigned raw = s_vbid;
    const unsigned gen = raw / (unsigned)GRID;
    const int vbid = (int)(raw % (unsigned)GRID);
    const unsigned V_AGG = 2u * gen + 1u;
    const unsigned V_INC = 2u * gen + 2u;

    const int b   = vbid % BB;        // b fastest: predecessors scheduled first
    const int j   = vbid / BB;
    const int f4  = tid % NF4;
    const int sub = tid / NF4;

    const int g0 = ((b * CC + 0) * TT + j * LCH) * FF;
    const int g1 = ((b * CC + 1) * TT + j * LCH) * FF;

    // ---- issue TMA loads immediately ----
    if (tid == 0) {
        mbar_expect_tx(mb, 2 * TILE_C_BYTES);
        bulk_ld(smem_u32(xs), x + g0, TILE_C_BYTES, mb);
        bulk_ld(smem_u32(xs + LCH * NF4), x + g1, TILE_C_BYTES, mb);
    }

    const float aLS = fpow(ALPHA_F, LS);    // alpha^5
    const float aB  = fpow(ALPHA_F, LCH);   // alpha^80
    const int ch = b * NCH + j;
    const float4 state4 = *(const float4*)(state + f4 * 4);

    mbar_wait_parity0(mb);

    // ---- phase 1: per-sub partial EMA from s=0 ----
    float4 P = make_float4(0.f, 0.f, 0.f, 0.f);
#pragma unroll
    for (int t = 0; t < LS; t++) {
        float4 a = xs[(sub * LS + t) * NF4 + f4];
        float4 c = xs[(LCH + sub * LS + t) * NF4 + f4];
        EMA4(P, a, c);
    }
    sX[sub * NF4 + f4] = P;
    __syncthreads();

    // A = full fold; Q = prefix fold up to own sub (start = aLS^sub * S + Q)
    float4 A = make_float4(0.f, 0.f, 0.f, 0.f);
    float4 Q = make_float4(0.f, 0.f, 0.f, 0.f);
    float aPow = 1.0f;                 // aLS^sub
#pragma unroll
    for (int k = 0; k < NSUB; k++) {
        float4 Pk = sX[k * NF4 + f4];
        FOLD4(A, aLS, Pk);
        if (k < sub) { FOLD4(Q, aLS, Pk); aPow *= aLS; }
    }
    __syncthreads();                   // sX reads done; safe to reuse as window

    // ---- publish aggregate FIRST (agg flow independent of lookback) ----
    if (sub == 0) {                    // tids 0..23, warp 0
        g_agg[ch * NF4 + f4] = A;
        __syncwarp(0x00FFFFFFu);
        if (tid == 0) { __threadfence(); st_release(&g_flag[ch], V_AGG); }
    }

    // ---- warp-parallel windowed lookback (leader-observed statuses) ----
    float4 S;
    if (j == 0) {
        S = state4;
    } else {
        float4 acc = make_float4(0.f, 0.f, 0.f, 0.f);
        float w = 1.0f;                // aB^(depth of window base)
        int base = j - 1;
        for (;;) {
            const int k = base - sub;
            // step 1: ONE leader per sub observes the flag
            if (f4 == 0 && k >= 0) {
                const unsigned* fl = &g_flag[b * NCH + k];
                unsigned st = ld_acquire(fl);
                int spins = 0;
                while (st < V_AGG) {
                    if (++spins > 32) { __nanosleep(64); spins = 0; }
                    st = ld_acquire(fl);
                }
                sSt[sub] = (st == V_INC) ? 2u : 1u;
            }
            __syncthreads();   // relay leader's acquire to the whole block

            // step 2: all threads load the value per the SHARED status
            if (k >= 0) {
                float4 v = (sSt[sub] == 2u) ? g_inc[(b * NCH + k) * NF4 + f4]
                                            : g_agg[(b * NCH + k) * NF4 + f4];
                sX[sub * NF4 + f4] = v;
            }
            __syncthreads();

            // step 3: uniform combine over the window
            const int lim = (base < NSUB - 1) ? base : (NSUB - 1);
            float wcur = w;
            bool done = false;
            for (int s = 0; s <= lim; s++) {
                float4 v = sX[s * NF4 + f4];
                unsigned stv = sSt[s];
                FMA4(acc, wcur, v);
                if (stv == 2u) { done = true; break; }       // inclusive found
                if (base - s == 0) {                          // consumed chunk-0 agg
                    float ws = wcur * aB;
                    FMA4(acc, ws, state4);
                    done = true; break;
                }
                wcur *= aB;
            }
            __syncthreads();           // window consumed before next rewrite
            if (done) break;
            base -= NSUB;              // guaranteed >= 0 here
            w = wcur;                  // = previous w * aB^NSUB
        }
        S = acc;
    }

    // ---- publish inclusive ASAP ----
    if (sub == 0) {
        float4 inc;
        inc.x = fmaf(aB, S.x, A.x);
        inc.y = fmaf(aB, S.y, A.y);
        inc.z = fmaf(aB, S.z, A.z);
        inc.w = fmaf(aB, S.w, A.w);
        g_inc[ch * NF4 + f4] = inc;
        __syncwarp(0x00FFFFFFu);
        if (tid == 0) { __threadfence(); st_release(&g_flag[ch], V_INC); }
    }

    // ---- start state: s4 = aLS^sub * S + Q ----
    float4 s4;
    s4.x = fmaf(aPow, S.x, Q.x);
    s4.y = fmaf(aPow, S.y, Q.y);
    s4.z = fmaf(aPow, S.z, Q.z);
    s4.w = fmaf(aPow, S.w, Q.w);

    // ---- phase 3: replay, compute y in place in smem ----
#pragma unroll
    for (int t = 0; t < LS; t++) {
        float4 a = xs[(sub * LS + t) * NF4 + f4];
        float4 c = xs[(LCH + sub * LS + t) * NF4 + f4];
        EMA4(s4, a, c);
        float4 r;
        r.x = rsqrtf(s4.x); r.y = rsqrtf(s4.y);
        r.z = rsqrtf(s4.z); r.w = rsqrtf(s4.w);
        float4 y0, y1;
        y0.x = a.x * r.x; y0.y = a.y * r.y; y0.z = a.z * r.z; y0.w = a.w * r.w;
        y1.x = c.x * r.x; y1.y = c.y * r.y; y1.z = c.z * r.z; y1.w = c.w * r.w;
        xs[(sub * LS + t) * NF4 + f4] = y0;
        xs[(LCH + sub * LS + t) * NF4 + f4] = y1;
    }

    if (write_state && j == NCH - 1 && sub == NSUB - 1) {
        *(float4*)(fstate + b * FF + f4 * 4) = s4;
    }

    __syncthreads();
    asm volatile("fence.proxy.async.shared::cta;" ::: "memory");
    if (tid == 0) {
        bulk_st(out + g0, smem_u32(xs), TILE_C_BYTES);
        bulk_st(out + g1, smem_u32(xs + LCH * NF4), TILE_C_BYTES);
        asm volatile("cp.async.bulk.commit_group;" ::: "memory");
        asm volatile("cp.async.bulk.wait_group 0;" ::: "memory");
    }
}

extern "C" void kernel_launch(void* const* d_in, const int* in_sizes, int n_in,
                              void* d_out, int out_size) {
    const float* feat  = (const float*)d_in[0];   // [B,C,T,F] f32
    const float* state = (const float*)d_in[1];   // [1,1,F]   f32
    float* out = (float*)d_out;

    const int n_out_main = BB * CC * TT * FF;     // 49,152,000
    int write_state = (out_size >= n_out_main + BB * FF) ? 1 : 0;
    float* fstate = out + n_out_main;

    cudaFuncSetAttribute(k_scan, cudaFuncAttributeMaxDynamicSharedMemorySize, DSMEM);
    k_scan<<<GRID, NTHR, DSMEM>>>(feat, state, out, fstate, write_state);
}